// round 14
// baseline (speedup 1.0000x reference)
#include <cuda_runtime.h>
#include <math.h>

#define NN 512
#define DD 384
#define HH 12
#define PCC 128
#define JH 256   /* j-half per logits block */

#define SCALAR_W 0.102062072615966f   /* 1/sqrt(96) */
#define POINT_WC 0.136082763487954f   /* 1/sqrt(54) */
#define PAIR_W   0.577350269189626f   /* 1/sqrt(3)  */

typedef unsigned long long u64;

__device__ __forceinline__ void ffma2(u64& d, u64 a, u64 b) {
    asm("fma.rn.f32x2 %0, %1, %2, %0;" : "+l"(d) : "l"(a), "l"(b));
}
__device__ __forceinline__ void fmul2(u64& d, u64 a) {
    asm("mul.rn.f32x2 %0, %0, %1;" : "+l"(d) : "l"(a));
}
__device__ __forceinline__ u64 pack2(float lo, float hi) {
    u64 r; asm("mov.b64 %0, {%1, %2};" : "=l"(r) : "f"(lo), "f"(hi)); return r;
}
__device__ __forceinline__ u64 dup2(float v) { return pack2(v, v); }
__device__ __forceinline__ float2 unpack2(u64 v) {
    float2 r; asm("mov.b64 {%0, %1}, %2;" : "=f"(r.x), "=f"(r.y) : "l"(v)); return r;
}

// ---------------- scratch (device globals; no allocation) ----------------
__device__ float g_qs[NN*DD];
__device__ float g_ks[NN*DD];
__device__ float g_vs[NN*DD];
__device__ float g_pq[NN*144];
__device__ float g_pk[NN*144];
__device__ float g_pv[NN*288];
__device__ float g_attn[(size_t)HH*NN*NN];   // RAW logits after logits_kernel
__device__ float g_ms[NN*HH*2];              // per (i,h): final max, sumexp
__device__ float g_msp[2*NN*HH*2];           // per-half partial (m, s)
__device__ float g_zpart[2*NN*HH*PCC];       // per-half unnormalized z
__device__ float g_z[NN*HH*PCC];
__device__ float g_outpg[NN*288];
__device__ float g_feat[NN*1152];

// ---------------- tiled fp32 GEMM body (FFMA2, double-buffered) -----------
__device__ __forceinline__ void gemm_body(const float* __restrict__ A,
                                          const float* __restrict__ B,
                                          const float* __restrict__ bias,
                                          float* __restrict__ C,
                                          int N, int K, int row0, int col0) {
    __shared__ float As[16][68];
    __shared__ float Bs[16][64];
    const int t  = threadIdx.x;
    const int tx = t & 15, ty = t >> 4;
    const int am = t >> 2, akg = t & 3;
    const int bk = t >> 4, bng = t & 15;
    const int bc = col0 + bng * 4;

    u64 acc2[4][2];
#pragma unroll
    for (int a = 0; a < 4; a++) { acc2[a][0] = 0ull; acc2[a][1] = 0ull; }

    float4 av = *(const float4*)(A + (size_t)(row0 + am) * K + akg * 4);
    float4 bv = make_float4(0.f, 0.f, 0.f, 0.f);
    if (bc < N) bv = *(const float4*)(B + (size_t)bk * N + bc);

    for (int k0 = 0; k0 < K; k0 += 16) {
        As[akg*4+0][am] = av.x;
        As[akg*4+1][am] = av.y;
        As[akg*4+2][am] = av.z;
        As[akg*4+3][am] = av.w;
        *(float4*)&Bs[bk][bng*4] = bv;
        __syncthreads();
        if (k0 + 16 < K) {
            av = *(const float4*)(A + (size_t)(row0 + am) * K + (k0 + 16) + akg * 4);
            if (bc < N) bv = *(const float4*)(B + (size_t)(k0 + 16 + bk) * N + bc);
        }
#pragma unroll
        for (int kk = 0; kk < 16; kk++) {
            float4 a4 = *(float4*)&As[kk][ty*4];
            ulonglong2 b2 = *(ulonglong2*)&Bs[kk][tx*4];
            u64 d;
            d = dup2(a4.x); ffma2(acc2[0][0], d, b2.x); ffma2(acc2[0][1], d, b2.y);
            d = dup2(a4.y); ffma2(acc2[1][0], d, b2.x); ffma2(acc2[1][1], d, b2.y);
            d = dup2(a4.z); ffma2(acc2[2][0], d, b2.x); ffma2(acc2[2][1], d, b2.y);
            d = dup2(a4.w); ffma2(acc2[3][0], d, b2.x); ffma2(acc2[3][1], d, b2.y);
        }
        __syncthreads();
    }
#pragma unroll
    for (int im = 0; im < 4; im++) {
        int r = row0 + ty*4 + im;
        float2 v0 = unpack2(acc2[im][0]);
        float2 v1 = unpack2(acc2[im][1]);
        float vv[4] = {v0.x, v0.y, v1.x, v1.y};
#pragma unroll
        for (int jn = 0; jn < 4; jn++) {
            int c = col0 + tx*4 + jn;
            if (c < N) C[(size_t)r * N + c] = vv[jn] + (bias ? bias[c] : 0.f);
        }
    }
}

// fused 6-way projection: one launch, grid (29, 8)
__global__ void proj_kernel(const float* __restrict__ x1d,
                            const float* __restrict__ w_sq,
                            const float* __restrict__ w_sk,
                            const float* __restrict__ w_sv,
                            const float* __restrict__ w_pq,
                            const float* __restrict__ w_pk,
                            const float* __restrict__ w_pv) {
    int bx = blockIdx.x;
    const float* B; float* C; int N; int c0;
    if (bx < 6)       { B = w_sq; C = g_qs; N = 384; c0 = bx; }
    else if (bx < 12) { B = w_sk; C = g_ks; N = 384; c0 = bx - 6; }
    else if (bx < 18) { B = w_sv; C = g_vs; N = 384; c0 = bx - 12; }
    else if (bx < 21) { B = w_pq; C = g_pq; N = 144; c0 = bx - 18; }
    else if (bx < 24) { B = w_pk; C = g_pk; N = 144; c0 = bx - 21; }
    else              { B = w_pv; C = g_pv; N = 288; c0 = bx - 24; }
    gemm_body(x1d, B, nullptr, C, N, 384, blockIdx.y * 64, c0 * 64);
}

// ---------------- final GEMM, 32-row tiles (grid 6 x 16 = 96 blocks) ------
__global__ void gemm32(const float* __restrict__ A, const float* __restrict__ B,
                       const float* __restrict__ bias, float* __restrict__ C,
                       int N, int K) {
    __shared__ float As[16][36];
    __shared__ float Bs[16][64];
    const int t  = threadIdx.x;
    const int tx = t & 15, ty = t >> 4;
    const int row0 = blockIdx.y * 32, col0 = blockIdx.x * 64;
    const int am = t >> 2, akg = t & 3;     // t<128 loads A
    const int bk = t >> 4, bng = t & 15;
    const int bc = col0 + bng * 4;

    u64 acc2[2][2];
    acc2[0][0] = acc2[0][1] = acc2[1][0] = acc2[1][1] = 0ull;

    float4 av = make_float4(0.f,0.f,0.f,0.f);
    if (t < 128) av = *(const float4*)(A + (size_t)(row0 + am) * K + akg * 4);
    float4 bv = make_float4(0.f, 0.f, 0.f, 0.f);
    if (bc < N) bv = *(const float4*)(B + (size_t)bk * N + bc);

    for (int k0 = 0; k0 < K; k0 += 16) {
        if (t < 128) {
            As[akg*4+0][am] = av.x;
            As[akg*4+1][am] = av.y;
            As[akg*4+2][am] = av.z;
            As[akg*4+3][am] = av.w;
        }
        *(float4*)&Bs[bk][bng*4] = bv;
        __syncthreads();
        if (k0 + 16 < K) {
            if (t < 128)
                av = *(const float4*)(A + (size_t)(row0 + am) * K + (k0 + 16) + akg * 4);
            if (bc < N) bv = *(const float4*)(B + (size_t)(k0 + 16 + bk) * N + bc);
        }
#pragma unroll
        for (int kk = 0; kk < 16; kk++) {
            float2 a2 = *(float2*)&As[kk][ty*2];
            ulonglong2 b2 = *(ulonglong2*)&Bs[kk][tx*4];
            u64 d;
            d = dup2(a2.x); ffma2(acc2[0][0], d, b2.x); ffma2(acc2[0][1], d, b2.y);
            d = dup2(a2.y); ffma2(acc2[1][0], d, b2.x); ffma2(acc2[1][1], d, b2.y);
        }
        __syncthreads();
    }
#pragma unroll
    for (int im = 0; im < 2; im++) {
        int r = row0 + ty*2 + im;
        float2 v0 = unpack2(acc2[im][0]);
        float2 v1 = unpack2(acc2[im][1]);
        float vv[4] = {v0.x, v0.y, v1.x, v1.y};
#pragma unroll
        for (int jn = 0; jn < 4; jn++) {
            int c = col0 + tx*4 + jn;
            if (c < N) C[(size_t)r * N + c] = vv[jn] + (bias ? bias[c] : 0.f);
        }
    }
}

// ---------------- in-place affine: pt <- R @ pt + T  (R = pose_r^T) --------
__global__ void affine_kernel(const float* __restrict__ pose_t,
                              const float* __restrict__ pose_r) {
    int idx = blockIdx.x * blockDim.x + threadIdx.x;
    if (idx >= NN * 192) return;
    int n = idx / 192, r = idx % 192;
    float* buf; int off;
    if (r < 48)      { buf = g_pq; off = n*144 + r*3; }
    else if (r < 96) { buf = g_pk; off = n*144 + (r-48)*3; }
    else             { buf = g_pv; off = n*288 + (r-96)*3; }
    float p0 = buf[off], p1 = buf[off+1], p2 = buf[off+2];
    const float* pr = pose_r + n*9;
    const float* T  = pose_t + n*3;
    float o0 = pr[0]*p0 + pr[3]*p1 + pr[6]*p2 + T[0];
    float o1 = pr[1]*p0 + pr[4]*p1 + pr[7]*p2 + T[1];
    float o2 = pr[2]*p0 + pr[5]*p1 + pr[8]*p2 + T[2];
    buf[off] = o0; buf[off+1] = o1; buf[off+2] = o2;
}

// ---------------- scalar attention base: S[h,i,j] = w * q.k ---------------
__global__ void scalar_attn_kernel() {
    __shared__ float s_q[32][68];
    __shared__ float s_k[32][68];
    const int h = blockIdx.z;
    const int i0 = blockIdx.y * 64, j0 = blockIdx.x * 64;
    const int t = threadIdx.x, tx = t & 15, ty = t >> 4;

    for (int idx = t; idx < 2048; idx += 256) {
        int r = idx >> 5, c = idx & 31;
        s_q[c][r] = g_qs[(i0 + r)*DD + h*32 + c];
        s_k[c][r] = g_ks[(j0 + r)*DD + h*32 + c];
    }
    __syncthreads();
    u64 acc2[4][2];
#pragma unroll
    for (int a = 0; a < 4; a++) { acc2[a][0] = 0ull; acc2[a][1] = 0ull; }
#pragma unroll
    for (int c = 0; c < 32; c++) {
        float4 a4 = *(float4*)&s_q[c][ty*4];
        ulonglong2 b2 = *(ulonglong2*)&s_k[c][tx*4];
        u64 d;
        d = dup2(a4.x); ffma2(acc2[0][0], d, b2.x); ffma2(acc2[0][1], d, b2.y);
        d = dup2(a4.y); ffma2(acc2[1][0], d, b2.x); ffma2(acc2[1][1], d, b2.y);
        d = dup2(a4.z); ffma2(acc2[2][0], d, b2.x); ffma2(acc2[2][1], d, b2.y);
        d = dup2(a4.w); ffma2(acc2[3][0], d, b2.x); ffma2(acc2[3][1], d, b2.y);
    }
#pragma unroll
    for (int im = 0; im < 4; im++) {
        float2 v0 = unpack2(acc2[im][0]);
        float2 v1 = unpack2(acc2[im][1]);
        float vv[4] = {v0.x, v0.y, v1.x, v1.y};
#pragma unroll
        for (int jn = 0; jn < 4; jn++)
            g_attn[((size_t)h*NN + i0 + ty*4 + im)*NN + j0 + tx*4 + jn] =
                SCALAR_W * vv[jn];
    }
}

// ---------------- fused logits + ONLINE softmax + z, j-split in halves ----
// grid (2, 512): blockIdx.x = j-half, blockIdx.y = query row i.
#define XS 66
#define LOGITS_SMEM_FLOATS (HH*JH + 128*XS + 1536 + 144 + 12 + 36)

__global__ void __launch_bounds__(256, 3)
logits_kernel(const float* __restrict__ x2d,
              const float* __restrict__ bias,
              const float* __restrict__ w_pb,
              const float* __restrict__ tpw) {
    extern __shared__ float sm[];
    float* s_logits = sm;                   // 12*256 = 3072
    float* s_xT     = sm + HH*JH;           // 128*66
    float* s_wpb    = s_xT + 128*XS;        // 1536
    float* s_qp     = s_wpb + 1536;         // 144
    float* s_pw     = s_qp + 144;           // 12
    float* s_m      = s_pw + 12;            // 12
    float* s_s      = s_m + 12;             // 12
    float* s_f      = s_s + 12;             // 12

    const int half = blockIdx.x;
    const int j0h  = half * JH;
    const int i    = blockIdx.y;
    const int t = threadIdx.x;
    const int warp = t >> 5, lane = t & 31;

    for (int idx = t; idx < 128*12; idx += 256) s_wpb[idx] = w_pb[idx];
    for (int idx = t; idx < 144;    idx += 256) s_qp[idx]  = g_pq[i*144 + idx];
    if (t < 12) {
        s_pw[t] = -0.5f * POINT_WC * log1pf(expf(tpw[t]));
        s_m[t] = -1e30f;
        s_s[t] = 0.f;
    }
    for (int idx = t; idx < HH*JH; idx += 256) {
        int h = idx >> 8, j = idx & (JH-1);
        s_logits[idx] = g_attn[((size_t)h*NN + i)*NN + j0h + j] + bias[i*NN + j0h + j];
    }
    __syncthreads();

    // ---- point attention for this j-half (one j per thread) ----
    {
        int j = t;   // 0..255
        const float* kp = g_pk + (j0h + j)*144;
#pragma unroll
        for (int h = 0; h < 12; h++) {
            float kq[12];
            *(float4*)&kq[0] = *(const float4*)(kp + h*12);
            *(float4*)&kq[4] = *(const float4*)(kp + h*12 + 4);
            *(float4*)&kq[8] = *(const float4*)(kp + h*12 + 8);
            float s = 0.f;
#pragma unroll
            for (int pt = 0; pt < 4; pt++) {
                int o = h*12 + pt*3;
                float dx = s_qp[o+0] - kq[pt*3+0];
                float dy = s_qp[o+1] - kq[pt*3+1];
                float dz = s_qp[o+2] - kq[pt*3+2];
                s += sqrtf(dx*dx + dy*dy + dz*dz);
            }
            s_logits[h*JH + j] += s_pw[h] * s;
        }
    }
    __syncthreads();

    // z accumulators: warp -> hg = warp&3 (3 heads), jg = warp>>2 (2 j-slices)
    const int hg = warp & 3;
    const int jg = warp >> 2;
    u64 zacc[4][3];
#pragma unroll
    for (int c = 0; c < 4; c++)
#pragma unroll
        for (int hh = 0; hh < 3; hh++) zacc[c][hh] = 0ull;

    const int jl = t & 63;
    const int ph = t >> 6;                 // 0..3, 32 p each (pair phase)

    for (int jc = 0; jc < JH; jc += 64) {
        // -- phase A: transpose-load x2d chunk (permuted p rows) --
        for (int idx = t; idx < 64*32; idx += 256) {
            int jj = idx >> 5, pg = idx & 31;
            float4 v = *(const float4*)(x2d + ((size_t)i*NN + j0h + jc + jj)*PCC + pg*4);
            s_xT[(pg     )*XS + jj] = v.x;
            s_xT[(pg + 32)*XS + jj] = v.y;
            s_xT[(pg + 64)*XS + jj] = v.z;
            s_xT[(pg + 96)*XS + jj] = v.w;
        }
        __syncthreads();

        // -- phase B: pair logits for this chunk (w: 3 aligned LDS.128) --
        u64 pa2[6];
#pragma unroll
        for (int hp = 0; hp < 6; hp++) pa2[hp] = 0ull;
#pragma unroll 8
        for (int q = 0; q < 32; q++) {
            int p = ph*32 + q;
            int row = (q & 3)*32 + ph*8 + (q >> 2);
            u64 xd = dup2(s_xT[row*XS + jl]);
            ulonglong2 wa = *(const ulonglong2*)(s_wpb + p*12);
            ulonglong2 wb = *(const ulonglong2*)(s_wpb + p*12 + 4);
            ulonglong2 wc = *(const ulonglong2*)(s_wpb + p*12 + 8);
            ffma2(pa2[0], xd, wa.x); ffma2(pa2[1], xd, wa.y);
            ffma2(pa2[2], xd, wb.x); ffma2(pa2[3], xd, wb.y);
            ffma2(pa2[4], xd, wc.x); ffma2(pa2[5], xd, wc.y);
        }
#pragma unroll
        for (int q = 0; q < 4; q++) {
            if (ph == q) {
#pragma unroll
                for (int hp = 0; hp < 6; hp++) {
                    float2 v = unpack2(pa2[hp]);
                    s_logits[(2*hp)*JH   + jc + jl] += PAIR_W * v.x;
                    s_logits[(2*hp+1)*JH + jc + jl] += PAIR_W * v.y;
                }
            }
            __syncthreads();
        }

        // -- phase B2: store raw logits; online (m,s) update; e in smem --
        if (warp < 6) {
            int h = warp*2 + (lane >> 4);
            int sl = lane & 15;
            float4 l4 = *(float4*)&s_logits[h*JH + jc + sl*4];
            *(float4*)(g_attn + ((size_t)h*NN + i)*NN + j0h + jc + sl*4) = l4;
            float cm = fmaxf(fmaxf(l4.x, l4.y), fmaxf(l4.z, l4.w));
#pragma unroll
            for (int o = 1; o < 16; o <<= 1)
                cm = fmaxf(cm, __shfl_xor_sync(0xffffffffu, cm, o));
            float m_old = s_m[h];
            float m_new = fmaxf(m_old, cm);
            float f = __expf(m_old - m_new);
            float4 e4;
            e4.x = __expf(l4.x - m_new);
            e4.y = __expf(l4.y - m_new);
            e4.z = __expf(l4.z - m_new);
            e4.w = __expf(l4.w - m_new);
            float cs = e4.x + e4.y + e4.z + e4.w;
#pragma unroll
            for (int o = 1; o < 16; o <<= 1)
                cs += __shfl_xor_sync(0xffffffffu, cs, o);
            *(float4*)&s_logits[h*JH + jc + sl*4] = e4;
            if (sl == 0) {
                s_s[h] = s_s[h] * f + cs;
                s_m[h] = m_new;
                s_f[h] = f;
            }
        }
        __syncthreads();

        // -- phase C: rescale + accumulate z (3 heads/warp, 32-j slices) --
        {
            u64 f2[3];
#pragma unroll
            for (int hh = 0; hh < 3; hh++) f2[hh] = dup2(s_f[hg*3 + hh]);
#pragma unroll
            for (int c = 0; c < 4; c++)
#pragma unroll
                for (int hh = 0; hh < 3; hh++) fmul2(zacc[c][hh], f2[hh]);
#pragma unroll
            for (int jj = jg*32; jj < jg*32 + 32; jj += 4) {
                u64 x2a[4], x2b[4];
#pragma unroll
                for (int c = 0; c < 4; c++) {
                    x2a[c] = *(const u64*)&s_xT[(c*32 + lane)*XS + jj];
                    x2b[c] = *(const u64*)&s_xT[(c*32 + lane)*XS + jj + 2];
                }
#pragma unroll
                for (int hh = 0; hh < 3; hh++) {
                    ulonglong2 a2 =
                        *(const ulonglong2*)&s_logits[(hg*3 + hh)*JH + jc + jj];
#pragma unroll
                    for (int c = 0; c < 4; c++) {
                        ffma2(zacc[c][hh], a2.x, x2a[c]);
                        ffma2(zacc[c][hh], a2.y, x2b[c]);
                    }
                }
            }
        }
        __syncthreads();
    }

    // ---- reduce 2 j-slice partials; write UNNORMALIZED z-partial + (m,s) --
    float* s_red = s_xT;   // 8*384 = 3072 floats
#pragma unroll
    for (int c = 0; c < 4; c++)
#pragma unroll
        for (int hh = 0; hh < 3; hh++) {
            float2 v = unpack2(zacc[c][hh]);
            s_red[warp*384 + hh*128 + 4*lane + c] = v.x + v.y;
        }
    __syncthreads();
    for (int idx = t; idx < 1536; idx += 256) {
        int h = idx >> 7, p = idx & 127;
        int hg2 = h / 3, hh = h % 3;
        float s = s_red[hg2*384 + hh*128 + p] + s_red[(4 + hg2)*384 + hh*128 + p];
        g_zpart[((size_t)half*NN + i)*1536 + h*128 + p] = s;
    }
    if (t < 12) {
        g_msp[((size_t)half*NN + i)*HH*2 + t*2 + 0] = s_m[t];
        g_msp[((size_t)half*NN + i)*HH*2 + t*2 + 1] = s_s[t];
    }
}

// ---------------- combine the two j-halves: final (m,s) + normalized z ----
__global__ void combine_kernel() {
    __shared__ float c0[12], c1[12];
    const int i = blockIdx.x;
    const int t = threadIdx.x;   // 256
    if (t < 12) {
        float m0 = g_msp[(size_t)i*HH*2 + t*2 + 0];
        float s0 = g_msp[(size_t)i*HH*2 + t*2 + 1];
        float m1 = g_msp[((size_t)NN + i)*HH*2 + t*2 + 0];
        float s1 = g_msp[((size_t)NN + i)*HH*2 + t*2 + 1];
        float m = fmaxf(m0, m1);
        float f0 = __expf(m0 - m), f1 = __expf(m1 - m);
        float s = s0*f0 + s1*f1;
        g_ms[(i*HH + t)*2 + 0] = m;
        g_ms[(i*HH + t)*2 + 1] = s;
        c0[t] = f0 / s;
        c1[t] = f1 / s;
    }
    __syncthreads();
    for (int idx = t; idx < 1536; idx += 256) {
        int h = idx >> 7;
        float z = g_zpart[(size_t)i*1536 + idx] * c0[h]
                + g_zpart[((size_t)NN + i)*1536 + idx] * c1[h];
        g_z[(size_t)i*1536 + idx] = z;
    }
}

// ---------------- attn @ [v_s | v_p] per head, 32-row tiles ----------------
__global__ void attn_apply_kernel() {
    __shared__ float s_a[32][68];
    __shared__ float s_v[64][64];
    __shared__ float s_m32[32];
    __shared__ float s_is32[32];
    const int h  = blockIdx.y;
    const int i0 = blockIdx.x * 32;
    const int t = threadIdx.x, tx = t & 15, ty = t >> 4;
    if (t < 32) {
        s_m32[t]  = g_ms[((i0 + t)*HH + h)*2 + 0];
        s_is32[t] = 1.0f / g_ms[((i0 + t)*HH + h)*2 + 1];
    }
    u64 acc2[2][2];
    acc2[0][0] = acc2[0][1] = acc2[1][0] = acc2[1][1] = 0ull;

    for (int j0 = 0; j0 < NN; j0 += 64) {
        __syncthreads();
        for (int idx = t; idx < 32*16; idx += 256) {
            int ii = idx >> 4, jg = idx & 15;
            float4 l4 = *(const float4*)(g_attn + ((size_t)h*NN + i0 + ii)*NN + j0 + jg*4);
            float m = s_m32[ii], is = s_is32[ii];
            float4 e4;
            e4.x = __expf(l4.x - m) * is;
            e4.y = __expf(l4.y - m) * is;
            e4.z = __expf(l4.z - m) * is;
            e4.w = __expf(l4.w - m) * is;
            *(float4*)&s_a[ii][jg*4] = e4;
        }
        for (int idx = t; idx < 64*64; idx += 256) {
            int jj = idx >> 6, c = idx & 63;
            int j = j0 + jj;
            float val = 0.f;
            if (c < 32)      val = g_vs[j*DD + h*32 + c];
            else if (c < 56) val = g_pv[j*288 + h*24 + (c - 32)];
            s_v[jj][c] = val;
        }
        __syncthreads();
#pragma unroll 4
        for (int jj = 0; jj < 64; jj++) {
            float a0 = s_a[ty*2+0][jj];
            float a1 = s_a[ty*2+1][jj];
            ulonglong2 b2 = *(ulonglong2*)&s_v[jj][tx*4];
            u64 d;
            d = dup2(a0); ffma2(acc2[0][0], d, b2.x); ffma2(acc2[0][1], d, b2.y);
            d = dup2(a1); ffma2(acc2[1][0], d, b2.x); ffma2(acc2[1][1], d, b2.y);
        }
    }
#pragma unroll
    for (int im = 0; im < 2; im++) {
        int r = i0 + ty*2 + im;
        float2 v0 = unpack2(acc2[im][0]);
        float2 v1 = unpack2(acc2[im][1]);
        float vv[4] = {v0.x, v0.y, v1.x, v1.y};
#pragma unroll
        for (int jn = 0; jn < 4; jn++) {
            int c = tx*4 + jn;
            if (c < 32)      g_feat[(size_t)r*1152 + h*32 + c] = vv[jn];
            else if (c < 56) g_outpg[r*288 + h*24 + (c - 32)]  = vv[jn];
        }
    }
}

// ---------------- tail: pairv (z @ w_pairv) + pose (inv affine + norms) ----
__global__ void tail_kernel(const float* __restrict__ w_pairv,
                            const float* __restrict__ pose_t,
                            const float* __restrict__ pose_r) {
    __shared__ float s_z[12*128];
    __shared__ float s_pr[9];
    __shared__ float s_T[3];
    const int i = blockIdx.x;
    const int t = threadIdx.x;   // 384 threads
    for (int idx = t; idx < 1536; idx += 384) s_z[idx] = g_z[(size_t)i*1536 + idx];
    if (t < 9) s_pr[t] = pose_r[i*9 + t];
    if (t < 3) s_T[t]  = pose_t[i*3 + t];
    __syncthreads();

    {
        int h = t >> 5;
        const float* zrow = s_z + h*128;
        float acc = 0.f;
#pragma unroll 8
        for (int p = 0; p < 128; p++) acc += zrow[p] * w_pairv[p*DD + t];
        g_feat[(size_t)i*1152 + 672 + t] = acc;
    }
    if (t < 96) {
        int h = t >> 3, pt = t & 7;
        int o = h*24 + pt*3;
        float d0 = g_outpg[i*288 + o+0] - s_T[0];
        float d1 = g_outpg[i*288 + o+1] - s_T[1];
        float d2 = g_outpg[i*288 + o+2] - s_T[2];
        float o0 = s_pr[0]*d0 + s_pr[1]*d1 + s_pr[2]*d2;
        float o1 = s_pr[3]*d0 + s_pr[4]*d1 + s_pr[5]*d2;
        float o2 = s_pr[6]*d0 + s_pr[7]*d1 + s_pr[8]*d2;
        g_feat[(size_t)i*1152 + 384 + o+0] = o0;
        g_feat[(size_t)i*1152 + 384 + o+1] = o1;
        g_feat[(size_t)i*1152 + 384 + o+2] = o2;
        g_feat[(size_t)i*1152 + 1056 + h*8 + pt] = sqrtf(o0*o0 + o1*o1 + o2*o2);
    }
}

// ---------------- launcher -------------------------------------------------
extern "C" void kernel_launch(void* const* d_in, const int* in_sizes, int n_in,
                              void* d_out, int out_size) {
    const float* x1d    = (const float*)d_in[0];
    const float* x2d    = (const float*)d_in[1];
    const float* pose_t = (const float*)d_in[2];
    const float* pose_r = (const float*)d_in[3];
    const float* bias   = (const float*)d_in[4];
    const float* w_sq   = (const float*)d_in[5];
    const float* w_sk   = (const float*)d_in[6];
    const float* w_sv   = (const float*)d_in[7];
    const float* w_pb   = (const float*)d_in[8];
    const float* w_pq   = (const float*)d_in[9];
    const float* w_pk   = (const float*)d_in[10];
    const float* w_pv   = (const float*)d_in[11];
    const float* tpw    = (const float*)d_in[12];
    const float* w_pairv= (const float*)d_in[13];
    const float* w_out  = (const float*)d_in[14];
    const float* b_out  = (const float*)d_in[15];
    float* out = (float*)d_out;

    float* feat;
    cudaGetSymbolAddress((void**)&feat, g_feat);

    const int LOGITS_SMEM = LOGITS_SMEM_FLOATS * 4;
    static int smem_set = 0;
    if (!smem_set) {
        cudaFuncSetAttribute(logits_kernel,
                             cudaFuncAttributeMaxDynamicSharedMemorySize, LOGITS_SMEM);
        smem_set = 1;
    }

    dim3 blk(256);
    proj_kernel<<<dim3(29, 8), blk>>>(x1d, w_sq, w_sk, w_sv, w_pq, w_pk, w_pv);
    affine_kernel<<<384, 256>>>(pose_t, pose_r);
    scalar_attn_kernel<<<dim3(8, 8, 12), blk>>>();
    logits_kernel<<<dim3(2, 512), blk, LOGITS_SMEM>>>(x2d, bias, w_pb, tpw);
    combine_kernel<<<512, 256>>>();
    attn_apply_kernel<<<dim3(16, 12), blk>>>();
    tail_kernel<<<512, 384>>>(w_pairv, pose_t, pose_r);
    gemm32<<<dim3(6, 16), blk>>>(feat, w_out, b_out, out, 384, 1152);
}

// round 15
// speedup vs baseline: 1.3839x; 1.3839x over previous
#include <cuda_runtime.h>
#include <math.h>

#define NN 512
#define DD 384
#define HH 12
#define PCC 128

#define SCALAR_W 0.102062072615966f   /* 1/sqrt(96) */
#define POINT_WC 0.136082763487954f   /* 1/sqrt(54) */
#define PAIR_W   0.577350269189626f   /* 1/sqrt(3)  */

typedef unsigned long long u64;

__device__ __forceinline__ void ffma2(u64& d, u64 a, u64 b) {
    asm("fma.rn.f32x2 %0, %1, %2, %0;" : "+l"(d) : "l"(a), "l"(b));
}
__device__ __forceinline__ void fmul2(u64& d, u64 a) {
    asm("mul.rn.f32x2 %0, %0, %1;" : "+l"(d) : "l"(a));
}
__device__ __forceinline__ u64 pack2(float lo, float hi) {
    u64 r; asm("mov.b64 %0, {%1, %2};" : "=l"(r) : "f"(lo), "f"(hi)); return r;
}
__device__ __forceinline__ u64 dup2(float v) { return pack2(v, v); }
__device__ __forceinline__ float2 unpack2(u64 v) {
    float2 r; asm("mov.b64 {%0, %1}, %2;" : "=f"(r.x), "=f"(r.y) : "l"(v)); return r;
}

// ---------------- scratch (device globals; no allocation) ----------------
__device__ float g_qs[NN*DD];
__device__ float g_ks[NN*DD];
__device__ float g_vs[NN*DD];
__device__ float g_pq[NN*144];
__device__ float g_pk[NN*144];
__device__ float g_pv[NN*288];
__device__ float g_attn[(size_t)HH*NN*NN];   // RAW logits after logits_kernel
__device__ float g_ms[NN*HH*2];              // per (i,h): max, sumexp
__device__ float g_z[NN*HH*PCC];
__device__ float g_outpg[NN*288];
__device__ float g_feat[NN*1152];

// ---------------- tiled fp32 GEMM body (FFMA2, double-buffered) -----------
__device__ __forceinline__ void gemm_body(const float* __restrict__ A,
                                          const float* __restrict__ B,
                                          const float* __restrict__ bias,
                                          float* __restrict__ C,
                                          int N, int K, int row0, int col0) {
    __shared__ float As[16][68];
    __shared__ float Bs[16][64];
    const int t  = threadIdx.x;
    const int tx = t & 15, ty = t >> 4;
    const int am = t >> 2, akg = t & 3;
    const int bk = t >> 4, bng = t & 15;
    const int bc = col0 + bng * 4;

    u64 acc2[4][2];
#pragma unroll
    for (int a = 0; a < 4; a++) { acc2[a][0] = 0ull; acc2[a][1] = 0ull; }

    float4 av = *(const float4*)(A + (size_t)(row0 + am) * K + akg * 4);
    float4 bv = make_float4(0.f, 0.f, 0.f, 0.f);
    if (bc < N) bv = *(const float4*)(B + (size_t)bk * N + bc);

    for (int k0 = 0; k0 < K; k0 += 16) {
        As[akg*4+0][am] = av.x;
        As[akg*4+1][am] = av.y;
        As[akg*4+2][am] = av.z;
        As[akg*4+3][am] = av.w;
        *(float4*)&Bs[bk][bng*4] = bv;
        __syncthreads();
        if (k0 + 16 < K) {
            av = *(const float4*)(A + (size_t)(row0 + am) * K + (k0 + 16) + akg * 4);
            if (bc < N) bv = *(const float4*)(B + (size_t)(k0 + 16 + bk) * N + bc);
        }
#pragma unroll
        for (int kk = 0; kk < 16; kk++) {
            float4 a4 = *(float4*)&As[kk][ty*4];
            ulonglong2 b2 = *(ulonglong2*)&Bs[kk][tx*4];
            u64 d;
            d = dup2(a4.x); ffma2(acc2[0][0], d, b2.x); ffma2(acc2[0][1], d, b2.y);
            d = dup2(a4.y); ffma2(acc2[1][0], d, b2.x); ffma2(acc2[1][1], d, b2.y);
            d = dup2(a4.z); ffma2(acc2[2][0], d, b2.x); ffma2(acc2[2][1], d, b2.y);
            d = dup2(a4.w); ffma2(acc2[3][0], d, b2.x); ffma2(acc2[3][1], d, b2.y);
        }
        __syncthreads();
    }
#pragma unroll
    for (int im = 0; im < 4; im++) {
        int r = row0 + ty*4 + im;
        float2 v0 = unpack2(acc2[im][0]);
        float2 v1 = unpack2(acc2[im][1]);
        float vv[4] = {v0.x, v0.y, v1.x, v1.y};
#pragma unroll
        for (int jn = 0; jn < 4; jn++) {
            int c = col0 + tx*4 + jn;
            if (c < N) C[(size_t)r * N + c] = vv[jn] + (bias ? bias[c] : 0.f);
        }
    }
}

// fused 6-way projection: one launch, grid (29, 8)
__global__ void proj_kernel(const float* __restrict__ x1d,
                            const float* __restrict__ w_sq,
                            const float* __restrict__ w_sk,
                            const float* __restrict__ w_sv,
                            const float* __restrict__ w_pq,
                            const float* __restrict__ w_pk,
                            const float* __restrict__ w_pv) {
    int bx = blockIdx.x;
    const float* B; float* C; int N; int c0;
    if (bx < 6)       { B = w_sq; C = g_qs; N = 384; c0 = bx; }
    else if (bx < 12) { B = w_sk; C = g_ks; N = 384; c0 = bx - 6; }
    else if (bx < 18) { B = w_sv; C = g_vs; N = 384; c0 = bx - 12; }
    else if (bx < 21) { B = w_pq; C = g_pq; N = 144; c0 = bx - 18; }
    else if (bx < 24) { B = w_pk; C = g_pk; N = 144; c0 = bx - 21; }
    else              { B = w_pv; C = g_pv; N = 288; c0 = bx - 24; }
    gemm_body(x1d, B, nullptr, C, N, 384, blockIdx.y * 64, c0 * 64);
}

// ---------------- final GEMM, 32-row tiles (grid 6 x 16 = 96 blocks) ------
__global__ void gemm32(const float* __restrict__ A, const float* __restrict__ B,
                       const float* __restrict__ bias, float* __restrict__ C,
                       int N, int K) {
    __shared__ float As[16][36];
    __shared__ float Bs[16][64];
    const int t  = threadIdx.x;
    const int tx = t & 15, ty = t >> 4;
    const int row0 = blockIdx.y * 32, col0 = blockIdx.x * 64;
    const int am = t >> 2, akg = t & 3;     // t<128 loads A
    const int bk = t >> 4, bng = t & 15;
    const int bc = col0 + bng * 4;

    u64 acc2[2][2];
    acc2[0][0] = acc2[0][1] = acc2[1][0] = acc2[1][1] = 0ull;

    float4 av = make_float4(0.f,0.f,0.f,0.f);
    if (t < 128) av = *(const float4*)(A + (size_t)(row0 + am) * K + akg * 4);
    float4 bv = make_float4(0.f, 0.f, 0.f, 0.f);
    if (bc < N) bv = *(const float4*)(B + (size_t)bk * N + bc);

    for (int k0 = 0; k0 < K; k0 += 16) {
        if (t < 128) {
            As[akg*4+0][am] = av.x;
            As[akg*4+1][am] = av.y;
            As[akg*4+2][am] = av.z;
            As[akg*4+3][am] = av.w;
        }
        *(float4*)&Bs[bk][bng*4] = bv;
        __syncthreads();
        if (k0 + 16 < K) {
            if (t < 128)
                av = *(const float4*)(A + (size_t)(row0 + am) * K + (k0 + 16) + akg * 4);
            if (bc < N) bv = *(const float4*)(B + (size_t)(k0 + 16 + bk) * N + bc);
        }
#pragma unroll
        for (int kk = 0; kk < 16; kk++) {
            float2 a2 = *(float2*)&As[kk][ty*2];
            ulonglong2 b2 = *(ulonglong2*)&Bs[kk][tx*4];
            u64 d;
            d = dup2(a2.x); ffma2(acc2[0][0], d, b2.x); ffma2(acc2[0][1], d, b2.y);
            d = dup2(a2.y); ffma2(acc2[1][0], d, b2.x); ffma2(acc2[1][1], d, b2.y);
        }
        __syncthreads();
    }
#pragma unroll
    for (int im = 0; im < 2; im++) {
        int r = row0 + ty*2 + im;
        float2 v0 = unpack2(acc2[im][0]);
        float2 v1 = unpack2(acc2[im][1]);
        float vv[4] = {v0.x, v0.y, v1.x, v1.y};
#pragma unroll
        for (int jn = 0; jn < 4; jn++) {
            int c = col0 + tx*4 + jn;
            if (c < N) C[(size_t)r * N + c] = vv[jn] + (bias ? bias[c] : 0.f);
        }
    }
}

// ---------------- in-place affine: pt <- R @ pt + T  (R = pose_r^T) --------
__global__ void affine_kernel(const float* __restrict__ pose_t,
                              const float* __restrict__ pose_r) {
    int idx = blockIdx.x * blockDim.x + threadIdx.x;
    if (idx >= NN * 192) return;
    int n = idx / 192, r = idx % 192;
    float* buf; int off;
    if (r < 48)      { buf = g_pq; off = n*144 + r*3; }
    else if (r < 96) { buf = g_pk; off = n*144 + (r-48)*3; }
    else             { buf = g_pv; off = n*288 + (r-96)*3; }
    float p0 = buf[off], p1 = buf[off+1], p2 = buf[off+2];
    const float* pr = pose_r + n*9;
    const float* T  = pose_t + n*3;
    float o0 = pr[0]*p0 + pr[3]*p1 + pr[6]*p2 + T[0];
    float o1 = pr[1]*p0 + pr[4]*p1 + pr[7]*p2 + T[1];
    float o2 = pr[2]*p0 + pr[5]*p1 + pr[8]*p2 + T[2];
    buf[off] = o0; buf[off+1] = o1; buf[off+2] = o2;
}

// ---------------- scalar attention base: S[h,i,j] = w * q.k ---------------
__global__ void scalar_attn_kernel() {
    __shared__ float s_q[32][68];
    __shared__ float s_k[32][68];
    const int h = blockIdx.z;
    const int i0 = blockIdx.y * 64, j0 = blockIdx.x * 64;
    const int t = threadIdx.x, tx = t & 15, ty = t >> 4;

    for (int idx = t; idx < 2048; idx += 256) {
        int r = idx >> 5, c = idx & 31;
        s_q[c][r] = g_qs[(i0 + r)*DD + h*32 + c];
        s_k[c][r] = g_ks[(j0 + r)*DD + h*32 + c];
    }
    __syncthreads();
    u64 acc2[4][2];
#pragma unroll
    for (int a = 0; a < 4; a++) { acc2[a][0] = 0ull; acc2[a][1] = 0ull; }
#pragma unroll
    for (int c = 0; c < 32; c++) {
        float4 a4 = *(float4*)&s_q[c][ty*4];
        ulonglong2 b2 = *(ulonglong2*)&s_k[c][tx*4];
        u64 d;
        d = dup2(a4.x); ffma2(acc2[0][0], d, b2.x); ffma2(acc2[0][1], d, b2.y);
        d = dup2(a4.y); ffma2(acc2[1][0], d, b2.x); ffma2(acc2[1][1], d, b2.y);
        d = dup2(a4.z); ffma2(acc2[2][0], d, b2.x); ffma2(acc2[2][1], d, b2.y);
        d = dup2(a4.w); ffma2(acc2[3][0], d, b2.x); ffma2(acc2[3][1], d, b2.y);
    }
#pragma unroll
    for (int im = 0; im < 4; im++) {
        float2 v0 = unpack2(acc2[im][0]);
        float2 v1 = unpack2(acc2[im][1]);
        float vv[4] = {v0.x, v0.y, v1.x, v1.y};
#pragma unroll
        for (int jn = 0; jn < 4; jn++)
            g_attn[((size_t)h*NN + i0 + ty*4 + im)*NN + j0 + tx*4 + jn] =
                SCALAR_W * vv[jn];
    }
}

// ---------------- fused logits + ONLINE softmax + z (single x2d pass) -----
#define XS 66
#define LOGITS_SMEM_FLOATS (6144 + 128*XS + 1536 + 144 + 12 + 36)

__global__ void __launch_bounds__(256, 3)
logits_kernel(const float* __restrict__ x2d,
              const float* __restrict__ bias,
              const float* __restrict__ w_pb,
              const float* __restrict__ tpw) {
    extern __shared__ float sm[];
    float* s_logits = sm;                   // 6144
    float* s_xT     = sm + 6144;            // 128*66
    float* s_wpb    = s_xT + 128*XS;        // 1536
    float* s_qp     = s_wpb + 1536;         // 144
    float* s_pw     = s_qp + 144;           // 12
    float* s_m      = s_pw + 12;            // 12
    float* s_s      = s_m + 12;             // 12
    float* s_f      = s_s + 12;             // 12

    const int i = blockIdx.x;
    const int t = threadIdx.x;
    const int warp = t >> 5, lane = t & 31;

    for (int idx = t; idx < 128*12; idx += 256) s_wpb[idx] = w_pb[idx];
    for (int idx = t; idx < 144;    idx += 256) s_qp[idx]  = g_pq[i*144 + idx];
    if (t < 12) {
        s_pw[t] = -0.5f * POINT_WC * log1pf(expf(tpw[t]));
        s_m[t] = -1e30f;
        s_s[t] = 0.f;
    }
    for (int idx = t; idx < 12*512; idx += 256) {
        int h = idx >> 9, j = idx & 511;
        s_logits[idx] = g_attn[((size_t)h*NN + i)*NN + j] + bias[i*NN + j];
    }
    __syncthreads();

    // ---- point attention (adds into s_logits) ----
    for (int j = t; j < NN; j += 256) {
        const float* kp = g_pk + j*144;
#pragma unroll
        for (int h = 0; h < 12; h++) {
            float kq[12];
            *(float4*)&kq[0] = *(const float4*)(kp + h*12);
            *(float4*)&kq[4] = *(const float4*)(kp + h*12 + 4);
            *(float4*)&kq[8] = *(const float4*)(kp + h*12 + 8);
            float s = 0.f;
#pragma unroll
            for (int pt = 0; pt < 4; pt++) {
                int o = h*12 + pt*3;
                float dx = s_qp[o+0] - kq[pt*3+0];
                float dy = s_qp[o+1] - kq[pt*3+1];
                float dz = s_qp[o+2] - kq[pt*3+2];
                s += sqrtf(dx*dx + dy*dy + dz*dz);
            }
            s_logits[h*512 + j] += s_pw[h] * s;
        }
    }
    __syncthreads();

    // z accumulators: warp -> hg = warp&3 (3 heads), jg = warp>>2 (2 j-slices)
    const int hg = warp & 3;
    const int jg = warp >> 2;
    u64 zacc[4][3];
#pragma unroll
    for (int c = 0; c < 4; c++)
#pragma unroll
        for (int hh = 0; hh < 3; hh++) zacc[c][hh] = 0ull;

    const int jl = t & 63;
    const int ph = t >> 6;                 // 0..3, 32 p each (pair phase)

    for (int jc = 0; jc < NN; jc += 64) {
        // -- phase A: transpose-load x2d chunk (permuted p rows) --
        for (int idx = t; idx < 64*32; idx += 256) {
            int jj = idx >> 5, pg = idx & 31;
            float4 v = *(const float4*)(x2d + ((size_t)i*NN + jc + jj)*PCC + pg*4);
            s_xT[(pg     )*XS + jj] = v.x;
            s_xT[(pg + 32)*XS + jj] = v.y;
            s_xT[(pg + 64)*XS + jj] = v.z;
            s_xT[(pg + 96)*XS + jj] = v.w;
        }
        __syncthreads();

        // -- phase B: pair logits for this chunk (w: 3 aligned LDS.128) --
        u64 pa2[6];
#pragma unroll
        for (int hp = 0; hp < 6; hp++) pa2[hp] = 0ull;
#pragma unroll 8
        for (int q = 0; q < 32; q++) {
            int p = ph*32 + q;
            int row = (q & 3)*32 + ph*8 + (q >> 2);
            u64 xd = dup2(s_xT[row*XS + jl]);
            ulonglong2 wa = *(const ulonglong2*)(s_wpb + p*12);
            ulonglong2 wb = *(const ulonglong2*)(s_wpb + p*12 + 4);
            ulonglong2 wc = *(const ulonglong2*)(s_wpb + p*12 + 8);
            ffma2(pa2[0], xd, wa.x); ffma2(pa2[1], xd, wa.y);
            ffma2(pa2[2], xd, wb.x); ffma2(pa2[3], xd, wb.y);
            ffma2(pa2[4], xd, wc.x); ffma2(pa2[5], xd, wc.y);
        }
#pragma unroll
        for (int q = 0; q < 4; q++) {
            if (ph == q) {
#pragma unroll
                for (int hp = 0; hp < 6; hp++) {
                    float2 v = unpack2(pa2[hp]);
                    s_logits[(2*hp)*512   + jc + jl] += PAIR_W * v.x;
                    s_logits[(2*hp+1)*512 + jc + jl] += PAIR_W * v.y;
                }
            }
            __syncthreads();
        }

        // -- phase B2: store raw logits; online (m,s) update; e in smem --
        if (warp < 6) {
            int h = warp*2 + (lane >> 4);
            int sl = lane & 15;
            float4 l4 = *(float4*)&s_logits[h*512 + jc + sl*4];
            *(float4*)(g_attn + ((size_t)h*NN + i)*NN + jc + sl*4) = l4;
            float cm = fmaxf(fmaxf(l4.x, l4.y), fmaxf(l4.z, l4.w));
#pragma unroll
            for (int o = 1; o < 16; o <<= 1)
                cm = fmaxf(cm, __shfl_xor_sync(0xffffffffu, cm, o));
            float m_old = s_m[h];
            float m_new = fmaxf(m_old, cm);
            float f = __expf(m_old - m_new);
            float4 e4;
            e4.x = __expf(l4.x - m_new);
            e4.y = __expf(l4.y - m_new);
            e4.z = __expf(l4.z - m_new);
            e4.w = __expf(l4.w - m_new);
            float cs = e4.x + e4.y + e4.z + e4.w;
#pragma unroll
            for (int o = 1; o < 16; o <<= 1)
                cs += __shfl_xor_sync(0xffffffffu, cs, o);
            *(float4*)&s_logits[h*512 + jc + sl*4] = e4;
            if (sl == 0) {
                s_s[h] = s_s[h] * f + cs;
                s_m[h] = m_new;
                s_f[h] = f;
            }
        }
        __syncthreads();

        // -- phase C: rescale + accumulate z (3 heads/warp, 32-j slices) --
        {
            u64 f2[3];
#pragma unroll
            for (int hh = 0; hh < 3; hh++) f2[hh] = dup2(s_f[hg*3 + hh]);
#pragma unroll
            for (int c = 0; c < 4; c++)
#pragma unroll
                for (int hh = 0; hh < 3; hh++) fmul2(zacc[c][hh], f2[hh]);
#pragma unroll
            for (int jj = jg*32; jj < jg*32 + 32; jj += 4) {
                u64 x2a[4], x2b[4];
#pragma unroll
                for (int c = 0; c < 4; c++) {
                    x2a[c] = *(const u64*)&s_xT[(c*32 + lane)*XS + jj];
                    x2b[c] = *(const u64*)&s_xT[(c*32 + lane)*XS + jj + 2];
                }
#pragma unroll
                for (int hh = 0; hh < 3; hh++) {
                    ulonglong2 a2 =
                        *(const ulonglong2*)&s_logits[(hg*3 + hh)*512 + jc + jj];
#pragma unroll
                    for (int c = 0; c < 4; c++) {
                        ffma2(zacc[c][hh], a2.x, x2a[c]);
                        ffma2(zacc[c][hh], a2.y, x2b[c]);
                    }
                }
            }
        }
        __syncthreads();
    }

    // ---- reduce 2 j-slice partials, divide by sum, write z + (m,s) -------
    float* s_red = s_xT;   // 8*384 = 3072 floats
#pragma unroll
    for (int c = 0; c < 4; c++)
#pragma unroll
        for (int hh = 0; hh < 3; hh++) {
            float2 v = unpack2(zacc[c][hh]);
            s_red[warp*384 + hh*128 + 4*lane + c] = v.x + v.y;
        }
    __syncthreads();
    for (int idx = t; idx < 1536; idx += 256) {
        int h = idx >> 7, p = idx & 127;
        int hg2 = h / 3, hh = h % 3;
        float s = s_red[hg2*384 + hh*128 + p] + s_red[(4 + hg2)*384 + hh*128 + p];
        g_z[(size_t)i*1536 + h*128 + p] = s / s_s[h];
    }
    if (t < 12) {
        g_ms[(i*HH + t)*2 + 0] = s_m[t];
        g_ms[(i*HH + t)*2 + 1] = s_s[t];
    }
}

// ---------------- attn @ [v_s | v_p] per head, 32-row tiles ----------------
__global__ void attn_apply_kernel() {
    __shared__ float s_a[32][68];
    __shared__ float s_v[64][64];
    __shared__ float s_m32[32];
    __shared__ float s_is32[32];
    const int h  = blockIdx.y;
    const int i0 = blockIdx.x * 32;
    const int t = threadIdx.x, tx = t & 15, ty = t >> 4;
    if (t < 32) {
        s_m32[t]  = g_ms[((i0 + t)*HH + h)*2 + 0];
        s_is32[t] = 1.0f / g_ms[((i0 + t)*HH + h)*2 + 1];
    }
    u64 acc2[2][2];
    acc2[0][0] = acc2[0][1] = acc2[1][0] = acc2[1][1] = 0ull;

    for (int j0 = 0; j0 < NN; j0 += 64) {
        __syncthreads();
        for (int idx = t; idx < 32*16; idx += 256) {
            int ii = idx >> 4, jg = idx & 15;
            float4 l4 = *(const float4*)(g_attn + ((size_t)h*NN + i0 + ii)*NN + j0 + jg*4);
            float m = s_m32[ii], is = s_is32[ii];
            float4 e4;
            e4.x = __expf(l4.x - m) * is;
            e4.y = __expf(l4.y - m) * is;
            e4.z = __expf(l4.z - m) * is;
            e4.w = __expf(l4.w - m) * is;
            *(float4*)&s_a[ii][jg*4] = e4;
        }
        for (int idx = t; idx < 64*64; idx += 256) {
            int jj = idx >> 6, c = idx & 63;
            int j = j0 + jj;
            float val = 0.f;
            if (c < 32)      val = g_vs[j*DD + h*32 + c];
            else if (c < 56) val = g_pv[j*288 + h*24 + (c - 32)];
            s_v[jj][c] = val;
        }
        __syncthreads();
#pragma unroll 4
        for (int jj = 0; jj < 64; jj++) {
            float a0 = s_a[ty*2+0][jj];
            float a1 = s_a[ty*2+1][jj];
            ulonglong2 b2 = *(ulonglong2*)&s_v[jj][tx*4];
            u64 d;
            d = dup2(a0); ffma2(acc2[0][0], d, b2.x); ffma2(acc2[0][1], d, b2.y);
            d = dup2(a1); ffma2(acc2[1][0], d, b2.x); ffma2(acc2[1][1], d, b2.y);
        }
    }
#pragma unroll
    for (int im = 0; im < 2; im++) {
        int r = i0 + ty*2 + im;
        float2 v0 = unpack2(acc2[im][0]);
        float2 v1 = unpack2(acc2[im][1]);
        float vv[4] = {v0.x, v0.y, v1.x, v1.y};
#pragma unroll
        for (int jn = 0; jn < 4; jn++) {
            int c = tx*4 + jn;
            if (c < 32)      g_feat[(size_t)r*1152 + h*32 + c] = vv[jn];
            else if (c < 56) g_outpg[r*288 + h*24 + (c - 32)]  = vv[jn];
        }
    }
}

// ---------------- tail: pairv (z @ w_pairv) + pose (inv affine + norms) ----
__global__ void tail_kernel(const float* __restrict__ w_pairv,
                            const float* __restrict__ pose_t,
                            const float* __restrict__ pose_r) {
    __shared__ float s_z[12*128];
    __shared__ float s_pr[9];
    __shared__ float s_T[3];
    const int i = blockIdx.x;
    const int t = threadIdx.x;   // 384 threads
    for (int idx = t; idx < 1536; idx += 384) s_z[idx] = g_z[(size_t)i*1536 + idx];
    if (t < 9) s_pr[t] = pose_r[i*9 + t];
    if (t < 3) s_T[t]  = pose_t[i*3 + t];
    __syncthreads();

    {
        int h = t >> 5;
        const float* zrow = s_z + h*128;
        float acc = 0.f;
#pragma unroll 8
        for (int p = 0; p < 128; p++) acc += zrow[p] * w_pairv[p*DD + t];
        g_feat[(size_t)i*1152 + 672 + t] = acc;
    }
    if (t < 96) {
        int h = t >> 3, pt = t & 7;
        int o = h*24 + pt*3;
        float d0 = g_outpg[i*288 + o+0] - s_T[0];
        float d1 = g_outpg[i*288 + o+1] - s_T[1];
        float d2 = g_outpg[i*288 + o+2] - s_T[2];
        float o0 = s_pr[0]*d0 + s_pr[1]*d1 + s_pr[2]*d2;
        float o1 = s_pr[3]*d0 + s_pr[4]*d1 + s_pr[5]*d2;
        float o2 = s_pr[6]*d0 + s_pr[7]*d1 + s_pr[8]*d2;
        g_feat[(size_t)i*1152 + 384 + o+0] = o0;
        g_feat[(size_t)i*1152 + 384 + o+1] = o1;
        g_feat[(size_t)i*1152 + 384 + o+2] = o2;
        g_feat[(size_t)i*1152 + 1056 + h*8 + pt] = sqrtf(o0*o0 + o1*o1 + o2*o2);
    }
}

// ---------------- launcher -------------------------------------------------
extern "C" void kernel_launch(void* const* d_in, const int* in_sizes, int n_in,
                              void* d_out, int out_size) {
    const float* x1d    = (const float*)d_in[0];
    const float* x2d    = (const float*)d_in[1];
    const float* pose_t = (const float*)d_in[2];
    const float* pose_r = (const float*)d_in[3];
    const float* bias   = (const float*)d_in[4];
    const float* w_sq   = (const float*)d_in[5];
    const float* w_sk   = (const float*)d_in[6];
    const float* w_sv   = (const float*)d_in[7];
    const float* w_pb   = (const float*)d_in[8];
    const float* w_pq   = (const float*)d_in[9];
    const float* w_pk   = (const float*)d_in[10];
    const float* w_pv   = (const float*)d_in[11];
    const float* tpw    = (const float*)d_in[12];
    const float* w_pairv= (const float*)d_in[13];
    const float* w_out  = (const float*)d_in[14];
    const float* b_out  = (const float*)d_in[15];
    float* out = (float*)d_out;

    float* feat;
    cudaGetSymbolAddress((void**)&feat, g_feat);

    const int LOGITS_SMEM = LOGITS_SMEM_FLOATS * 4;
    static int smem_set = 0;
    if (!smem_set) {
        cudaFuncSetAttribute(logits_kernel,
                             cudaFuncAttributeMaxDynamicSharedMemorySize, LOGITS_SMEM);
        smem_set = 1;
    }

    dim3 blk(256);
    proj_kernel<<<dim3(29, 8), blk>>>(x1d, w_sq, w_sk, w_sv, w_pq, w_pk, w_pv);
    affine_kernel<<<384, 256>>>(pose_t, pose_r);
    scalar_attn_kernel<<<dim3(8, 8, 12), blk>>>();
    logits_kernel<<<512, 256, LOGITS_SMEM>>>(x2d, bias, w_pb, tpw);
    attn_apply_kernel<<<dim3(16, 12), blk>>>();
    tail_kernel<<<512, 384>>>(w_pairv, pose_t, pose_r);
    gemm32<<<dim3(6, 16), blk>>>(feat, w_out, b_out, out, 384, 1152);
}